// round 6
// baseline (speedup 1.0000x reference)
#include <cuda_runtime.h>
#include <cuda_bf16.h>
#include <math.h>
#include <stdint.h>

// Problem constants
#define B   256
#define T1  127
#define D   512
#define H   512
#define G   2048
#define NL  3
#define OUT_ENC ((size_t)B * T1 * D)

#define GRID 128
#define NT   256

typedef __nv_bfloat16 bf;

// ---------------------------------------------------------------------------
// Scratch
// ---------------------------------------------------------------------------
__device__ float g_pre0[(size_t)T1 * B * G];   // remapped: [t][b][tilec*64 + (q*16+j)]
__device__ bf g_hhi[2][NL][B * H];             // step-parity double buffer
__device__ bf g_hlo[2][NL][B * H];
__device__ bf g_wih_hi[NL * G * H];
__device__ bf g_wih_lo[NL * G * H];
__device__ bf g_whh_hi[NL * G * H];
__device__ bf g_whh_lo[NL * G * H];
__device__ bf g_xhi[(size_t)B * T1 * D];
__device__ bf g_xlo[(size_t)B * T1 * D];
__device__ unsigned g_flags[GRID];
__device__ unsigned g_rel;

// ---------------------------------------------------------------------------
// Flag-based grid barrier: per-CTA flag slots (no contended atomics).
// Generations are monotonic within a launch, base read from g_rel at start
// (end-of-launch state: all flags == rel, consistent across graph replays).
// ---------------------------------------------------------------------------
__device__ __forceinline__ void gbar(unsigned gen) {
    __syncthreads();
    if (threadIdx.x == 0) {
        __threadfence();
        ((volatile unsigned*)g_flags)[blockIdx.x] = gen;
    }
    if (blockIdx.x == 0) {
        if (threadIdx.x < GRID)
            while ((int)(((volatile unsigned*)g_flags)[threadIdx.x] - gen) < 0) {}
        __syncthreads();
        if (threadIdx.x == 0) {
            __threadfence();
            *(volatile unsigned*)&g_rel = gen;
        }
    }
    while ((int)(*(volatile unsigned*)&g_rel - gen) < 0) {}
    __threadfence();
    __syncthreads();
}

__device__ __forceinline__ float sigm(float x) { return 1.f / (1.f + expf(-x)); }

// ---------------------------------------------------------------------------
__device__ __forceinline__ void cp16(bf* dst, const bf* src) {
    uint32_t d = (uint32_t)__cvta_generic_to_shared(dst);
    asm volatile("cp.async.cg.shared.global [%0], [%1], 16;" :: "r"(d), "l"(src));
}
#define CP_COMMIT() asm volatile("cp.async.commit_group;" ::: "memory")
#define CP_WAIT1()  asm volatile("cp.async.wait_group 1;" ::: "memory")

__device__ __forceinline__ void ldm4(uint32_t addr, uint32_t r[4]) {
    asm volatile("ldmatrix.sync.aligned.m8n8.x4.shared.b16 {%0,%1,%2,%3}, [%4];"
                 : "=r"(r[0]), "=r"(r[1]), "=r"(r[2]), "=r"(r[3]) : "r"(addr));
}
__device__ __forceinline__ void mma16816(float c[4], const uint32_t a[4],
                                         uint32_t b0, uint32_t b1) {
    asm volatile(
        "mma.sync.aligned.m16n8k16.row.col.f32.bf16.bf16.f32 "
        "{%0,%1,%2,%3},{%4,%5,%6,%7},{%8,%9},{%0,%1,%2,%3};"
        : "+f"(c[0]), "+f"(c[1]), "+f"(c[2]), "+f"(c[3])
        : "r"(a[0]), "r"(a[1]), "r"(a[2]), "r"(a[3]), "r"(b0), "r"(b1));
}

// K-chunk = 64. Stage: 4 planes x 64 rows x 64 cols bf16 = 32KB; 3-stage ring.
#define STG_ELEMS 16384   // elems per stage
#define PLANE     4096    // elems per plane

// W gather: SMEM row r -> W row (r>>4)*512 + colbase + (r&15)  (gate quadrants)
// Fused K: chunks [0,8) from A1/W1; [8,nch) from A2/W2.
__device__ __forceinline__ void prefetch_chunk(
        const bf* __restrict__ A1hi, const bf* __restrict__ A1lo, int lda_a,
        const bf* __restrict__ W1hi, const bf* __restrict__ W1lo,
        const bf* __restrict__ A2hi, const bf* __restrict__ A2lo,
        const bf* __restrict__ W2hi, const bf* __restrict__ W2lo,
        int row0, int colbase, int kc, bf* stg) {
    const int r  = (threadIdx.x >> 2) & 63;
    const int cs = threadIdx.x & 3;
    const int wrow = ((r >> 4) << 9) + colbase + (r & 15);
    const bf *ahi, *alo, *whi, *wlo;
    int kbase;
    if (kc < 8) {
        kbase = kc * 64;
        ahi = A1hi; alo = A1lo; whi = W1hi; wlo = W1lo;
    } else {
        kbase = (kc - 8) * 64;
        ahi = A2hi; alo = A2lo; whi = W2hi; wlo = W2lo;
    }
    const bf* sa_hi = ahi + (size_t)(row0 + r) * lda_a + kbase;
    const bf* sa_lo = alo + (size_t)(row0 + r) * lda_a + kbase;
    const bf* sw_hi = whi + (size_t)wrow * 512 + kbase;
    const bf* sw_lo = wlo + (size_t)wrow * 512 + kbase;
#pragma unroll
    for (int u = 0; u < 2; u++) {
        int s = cs + u * 4;
        int col = s * 8;
        bf* d = stg + r * 64 + ((s ^ (r & 7)) * 8);
        cp16(d + 0 * PLANE, sa_hi + col);
        cp16(d + 1 * PLANE, sa_lo + col);
        cp16(d + 2 * PLANE, sw_hi + col);
        cp16(d + 3 * PLANE, sw_lo + col);
    }
}

// 64x64 tile, bf16 3-pass split, 3-stage cp.async ring, acc interleaved.
// nch counts 64-wide K chunks (8 per 512-K source).
__device__ void mm_tile(const bf* A1hi, const bf* A1lo, int lda_a,
                        const bf* W1hi, const bf* W1lo,
                        const bf* A2hi, const bf* A2lo,
                        const bf* W2hi, const bf* W2lo,
                        int row0, int colbase, int nch,
                        float acc[4][4], bf* smem) {
    const int lane = threadIdx.x & 31;
    const int warp = threadIdx.x >> 5;
    const int wr = warp >> 1, wc = warp & 1;
    const int arow  = wr * 16 + (lane & 15);
    const int ahalf = lane >> 4;
    const int nrl   = wc * 32 + ((lane >> 4) << 3) + (lane & 7);
    const int bhalf = (lane >> 3) & 1;
    const uint32_t sbase = (uint32_t)__cvta_generic_to_shared(smem);

    prefetch_chunk(A1hi,A1lo,lda_a,W1hi,W1lo,A2hi,A2lo,W2hi,W2lo,row0,colbase,0,smem);
    CP_COMMIT();
    prefetch_chunk(A1hi,A1lo,lda_a,W1hi,W1lo,A2hi,A2lo,W2hi,W2lo,row0,colbase,1,smem+STG_ELEMS);
    CP_COMMIT();

    for (int kc = 0; kc < nch; kc++) {
        CP_WAIT1();
        __syncthreads();
        if (kc + 2 < nch)
            prefetch_chunk(A1hi,A1lo,lda_a,W1hi,W1lo,A2hi,A2lo,W2hi,W2lo,
                           row0,colbase,kc+2, smem + ((kc+2)%3)*STG_ELEMS);
        CP_COMMIT();

        const uint32_t sb = sbase + (uint32_t)((kc % 3) * STG_ELEMS * 2);
#pragma unroll
        for (int sub = 0; sub < 4; sub++) {
            uint32_t ahi[4], alo[4];
            int aseg = (sub * 2 + ahalf) ^ (arow & 7);
            uint32_t aoff = (uint32_t)((arow * 64 + aseg * 8) * 2);
            ldm4(sb + 0 * 8192 + aoff, ahi);
            ldm4(sb + 1 * 8192 + aoff, alo);
            uint32_t bh0[4], bl0[4], bh1[4], bl1[4];
            {
                int nr = nrl;
                int bseg = (sub * 2 + bhalf) ^ (nr & 7);
                uint32_t boff = (uint32_t)((nr * 64 + bseg * 8) * 2);
                ldm4(sb + 2 * 8192 + boff, bh0);
                ldm4(sb + 3 * 8192 + boff, bl0);
            }
            {
                int nr = nrl + 16;
                int bseg = (sub * 2 + bhalf) ^ (nr & 7);
                uint32_t boff = (uint32_t)((nr * 64 + bseg * 8) * 2);
                ldm4(sb + 2 * 8192 + boff, bh1);
                ldm4(sb + 3 * 8192 + boff, bl1);
            }
            // round-robin across 4 accumulators (dep distance 4)
            mma16816(acc[0], ahi, bh0[0], bh0[1]);
            mma16816(acc[1], ahi, bh0[2], bh0[3]);
            mma16816(acc[2], ahi, bh1[0], bh1[1]);
            mma16816(acc[3], ahi, bh1[2], bh1[3]);
            mma16816(acc[0], ahi, bl0[0], bl0[1]);
            mma16816(acc[1], ahi, bl0[2], bl0[3]);
            mma16816(acc[2], ahi, bl1[0], bl1[1]);
            mma16816(acc[3], ahi, bl1[2], bl1[3]);
            mma16816(acc[0], alo, bh0[0], bh0[1]);
            mma16816(acc[1], alo, bh0[2], bh0[3]);
            mma16816(acc[2], alo, bh1[0], bh1[1]);
            mma16816(acc[3], alo, bh1[2], bh1[3]);
        }
    }
    __syncthreads();
}

__device__ __forceinline__ void acc_coord(int nt, int e, int& r, int& c) {
    const int lane = threadIdx.x & 31, warp = threadIdx.x >> 5;
    const int wr = warp >> 1, wc = warp & 1;
    r = wr * 16 + (lane >> 2) + ((e >> 1) ? 8 : 0);
    c = wc * 32 + nt * 8 + (lane & 3) * 2 + (e & 1);
}

// ---------------------------------------------------------------------------
__global__ void split_w_kernel(const float* __restrict__ wih,
                               const float* __restrict__ whh) {
    int idx = blockIdx.x * blockDim.x + threadIdx.x;
    if (idx >= NL * G * H) return;
    float a = wih[idx];
    bf h1 = __float2bfloat16(a);
    g_wih_hi[idx] = h1;
    g_wih_lo[idx] = __float2bfloat16(a - __bfloat162float(h1));
    float b = whh[idx];
    bf h2 = __float2bfloat16(b);
    g_whh_hi[idx] = h2;
    g_whh_lo[idx] = __float2bfloat16(b - __bfloat162float(h2));
}

// ---------------------------------------------------------------------------
// attn[b,d] = softmax_d( sum_t x[b,t,d]*attn_w[2H+t] )  — time-invariant.
// ---------------------------------------------------------------------------
__global__ void attn_kernel(const float* __restrict__ x, const float* __restrict__ aw,
                            float* __restrict__ out) {
    __shared__ float saw[T1];
    __shared__ float red[512];
    int b = blockIdx.x, d = threadIdx.x;
    if (d < T1) saw[d] = aw[2 * H + d];
    __syncthreads();
    const float* xb = x + (size_t)b * T1 * D;
    float acc = 0.f;
    for (int t = 0; t < T1; t++) acc += xb[(size_t)t * D + d] * saw[t];
    red[d] = acc;
    __syncthreads();
    for (int s = 256; s > 0; s >>= 1) {
        if (d < s) red[d] = fmaxf(red[d], red[d + s]);
        __syncthreads();
    }
    float mx = red[0];
    __syncthreads();
    float e = expf(acc - mx);
    red[d] = e;
    __syncthreads();
    for (int s = 256; s > 0; s >>= 1) {
        if (d < s) red[d] += red[d + s];
        __syncthreads();
    }
    float a = e / red[0];
    float* ob = out + (size_t)b * T1 * D;
    for (int t = 0; t < T1; t++) {
        float w = a * xb[(size_t)t * D + d];
        ob[(size_t)t * D + d] = w;
        bf hi = __float2bfloat16(w);
        size_t gi = (size_t)b * T1 * D + (size_t)t * D + d;
        g_xhi[gi] = hi;
        g_xlo[gi] = __float2bfloat16(w - __bfloat162float(hi));
    }
}

// ---------------------------------------------------------------------------
// pre0 (remapped layout): pre0[t][b][tilec*64 + c] = weighted@Wih0^T + biases
// ---------------------------------------------------------------------------
__global__ void __launch_bounds__(NT) pre_gemm_kernel(const float* __restrict__ bih,
                                                      const float* __restrict__ bhh) {
    __shared__ __align__(16) bf smem[3 * STG_ELEMS];
    int tstep = blockIdx.x >> 2;
    int b0    = (blockIdx.x & 3) * 64;
    int tilec = blockIdx.y;
    int colbase = tilec * 16;
    float acc[4][4] = {};
    mm_tile(g_xhi + (size_t)tstep * D, g_xlo + (size_t)tstep * D, T1 * D,
            g_wih_hi, g_wih_lo, 0, 0, 0, 0, b0, colbase, 8, acc, smem);
    size_t base = (size_t)tstep * B * G;
#pragma unroll
    for (int nt = 0; nt < 4; nt++)
#pragma unroll
        for (int e = 0; e < 4; e++) {
            int r, c;
            acc_coord(nt, e, r, c);
            int bcol = ((c >> 4) << 9) + colbase + (c & 15);
            g_pre0[base + (size_t)(b0 + r) * G + tilec * 64 + c] =
                acc[nt][e] + bih[bcol] + bhh[bcol];
        }
}

// ---------------------------------------------------------------------------
// Persistent recurrent kernel: 128 CTAs, 3 grid barriers per step.
// CTA tile: batch rows row0..+63, gate cols q*512+colbase+j (q=0..3, j=0..15).
// Cell state lives in CTA SMEM across all steps. h double-buffered by parity.
// ---------------------------------------------------------------------------
__global__ void __launch_bounds__(NT, 1) lstm_kernel(const float* __restrict__ bih,
                                                     const float* __restrict__ bhh,
                                                     float* __restrict__ out) {
    __shared__ __align__(16) bf smem[3 * STG_ELEMS];        // 96KB ring
    __shared__ float sg[64][65];                             // gate tile
    __shared__ float sc[NL][64 * 16];                        // cell state
    __shared__ float sbias[2][64];                           // layer 1,2 biases

    const int tile = blockIdx.x;
    const int row0    = (tile >> 5) * 64;
    const int tilec   = tile & 31;
    const int colbase = tilec * 16;
    const int tid = threadIdx.x;

    unsigned gen = *(volatile unsigned*)&g_rel;   // consistent base across replays

    for (int idx = blockIdx.x * NT + tid; idx < NL * B * H; idx += GRID * NT) {
        ((bf*)g_hhi[1])[idx] = __float2bfloat16(0.f);
        ((bf*)g_hlo[1])[idx] = __float2bfloat16(0.f);
    }
    for (int k = tid; k < NL * 64 * 16; k += NT) ((float*)sc)[k] = 0.f;
    if (tid < 128) {
        int l = (tid >> 6) + 1, c = tid & 63;
        int bcol = l * G + ((c >> 4) << 9) + colbase + (c & 15);
        sbias[l - 1][c] = bih[bcol] + bhh[bcol];
    }
    gbar(++gen);

    for (int t = 0; t < T1; t++) {
        const int np = t & 1, op = np ^ 1;
        for (int l = 0; l < NL; l++) {
            float acc[4][4] = {};
            if (l == 0) {
                mm_tile(g_hhi[op][0], g_hlo[op][0], 512,
                        g_whh_hi, g_whh_lo, 0, 0, 0, 0,
                        row0, colbase, 8, acc, smem);
            } else {
                mm_tile(g_hhi[op][l], g_hlo[op][l], 512,
                        g_whh_hi + (size_t)l * G * H, g_whh_lo + (size_t)l * G * H,
                        g_hhi[np][l - 1], g_hlo[np][l - 1],
                        g_wih_hi + (size_t)l * G * H, g_wih_lo + (size_t)l * G * H,
                        row0, colbase, 16, acc, smem);
            }
#pragma unroll
            for (int nt = 0; nt < 4; nt++)
#pragma unroll
                for (int e = 0; e < 4; e++) {
                    int r, c;
                    acc_coord(nt, e, r, c);
                    sg[r][c] = acc[nt][e];
                }
            __syncthreads();

            // CTA-local cell update (1024 cells, 4 per thread)
#pragma unroll
            for (int k = 0; k < 4; k++) {
                int idx = tid + k * NT;
                int b = idx >> 4, j = idx & 15;
                float gi = sg[b][j], gf = sg[b][16 + j],
                      gg = sg[b][32 + j], go = sg[b][48 + j];
                if (l == 0) {
                    const float* p = g_pre0 + (size_t)t * B * G
                                   + (size_t)(row0 + b) * G + tilec * 64;
                    gi += p[j]; gf += p[16 + j]; gg += p[32 + j]; go += p[48 + j];
                } else {
                    const float* sb2 = sbias[l - 1];
                    gi += sb2[j]; gf += sb2[16 + j]; gg += sb2[32 + j]; go += sb2[48 + j];
                }
                float i_ = sigm(gi), f_ = sigm(gf), g_ = tanhf(gg), o_ = sigm(go);
                float cn = f_ * sc[l][idx] + i_ * g_;
                float hn = o_ * tanhf(cn);
                sc[l][idx] = cn;
                bf hh = __float2bfloat16(hn);
                size_t hidx = (size_t)(row0 + b) * H + colbase + j;
                g_hhi[np][l][hidx] = hh;
                g_hlo[np][l][hidx] = __float2bfloat16(hn - __bfloat162float(hh));
                if (l == NL - 1)
                    out[OUT_ENC + (size_t)(row0 + b) * T1 * H + (size_t)t * H
                        + colbase + j] = hn;
            }
            gbar(++gen);
        }
    }
}

// ---------------------------------------------------------------------------
extern "C" void kernel_launch(void* const* d_in, const int* in_sizes, int n_in,
                              void* d_out, int out_size) {
    const float* x   = (const float*)d_in[0];
    const float* wih = (const float*)d_in[1];
    const float* whh = (const float*)d_in[2];
    const float* bih = (const float*)d_in[3];
    const float* bhh = (const float*)d_in[4];
    const float* aw  = (const float*)d_in[5];
    float* out = (float*)d_out;

    split_w_kernel<<<(NL * G * H + 255) / 256, 256>>>(wih, whh);
    attn_kernel<<<B, 512>>>(x, aw, out);
    dim3 pgrid(T1 * 4, G / 64);
    pre_gemm_kernel<<<pgrid, NT>>>(bih, bhh);
    lstm_kernel<<<GRID, NT>>>(bih, bhh, out);
}

// round 7
// speedup vs baseline: 1.0755x; 1.0755x over previous
#include <cuda_runtime.h>
#include <cuda_bf16.h>
#include <math.h>
#include <stdint.h>

// Problem constants
#define B   256
#define T1  127
#define D   512
#define H   512
#define G   2048
#define NL  3
#define GH  (G * H)
#define OUT_ENC ((size_t)B * T1 * D)

#define GRID 128
#define NT   256

typedef __nv_bfloat16 bf;

// ---------------------------------------------------------------------------
// Scratch
// ---------------------------------------------------------------------------
__device__ float g_pre0[(size_t)T1 * B * G];   // remapped: [t][b][tilec*64 + (q*16+j)]
__device__ bf g_hhi[2][NL][B * H];             // wave-parity double buffer
__device__ bf g_hlo[2][NL][B * H];
__device__ bf g_wih_hi[NL * GH];
__device__ bf g_wih_lo[NL * GH];
__device__ bf g_whh_hi[NL * GH];
__device__ bf g_whh_lo[NL * GH];
__device__ bf g_xhi[(size_t)B * T1 * D];
__device__ bf g_xlo[(size_t)B * T1 * D];
__device__ unsigned g_flags[GRID];
__device__ unsigned g_rel;

// ---------------------------------------------------------------------------
// Flag-based grid barrier (per-CTA flag slots, no contended atomics).
// ---------------------------------------------------------------------------
__device__ __forceinline__ void gbar(unsigned gen) {
    __syncthreads();
    if (threadIdx.x == 0) {
        __threadfence();
        ((volatile unsigned*)g_flags)[blockIdx.x] = gen;
    }
    if (blockIdx.x == 0) {
        if (threadIdx.x < GRID)
            while ((int)(((volatile unsigned*)g_flags)[threadIdx.x] - gen) < 0) {}
        __syncthreads();
        if (threadIdx.x == 0) {
            __threadfence();
            *(volatile unsigned*)&g_rel = gen;
        }
    }
    while ((int)(*(volatile unsigned*)&g_rel - gen) < 0) {}
    __threadfence();
    __syncthreads();
}

__device__ __forceinline__ float sigm(float x) { return 1.f / (1.f + expf(-x)); }

// ---------------------------------------------------------------------------
__device__ __forceinline__ void cp16(bf* dst, const bf* src) {
    uint32_t d = (uint32_t)__cvta_generic_to_shared(dst);
    asm volatile("cp.async.cg.shared.global [%0], [%1], 16;" :: "r"(d), "l"(src));
}
#define CP_COMMIT() asm volatile("cp.async.commit_group;" ::: "memory")
#define CP_WAIT1()  asm volatile("cp.async.wait_group 1;" ::: "memory")

__device__ __forceinline__ void ldm4(uint32_t addr, uint32_t r[4]) {
    asm volatile("ldmatrix.sync.aligned.m8n8.x4.shared.b16 {%0,%1,%2,%3}, [%4];"
                 : "=r"(r[0]), "=r"(r[1]), "=r"(r[2]), "=r"(r[3]) : "r"(addr));
}
__device__ __forceinline__ void mma16816(float c[4], const uint32_t a[4],
                                         uint32_t b0, uint32_t b1) {
    asm volatile(
        "mma.sync.aligned.m16n8k16.row.col.f32.bf16.bf16.f32 "
        "{%0,%1,%2,%3},{%4,%5,%6,%7},{%8,%9},{%0,%1,%2,%3};"
        : "+f"(c[0]), "+f"(c[1]), "+f"(c[2]), "+f"(c[3])
        : "r"(a[0]), "r"(a[1]), "r"(a[2]), "r"(a[3]), "r"(b0), "r"(b1));
}

// K-chunk = 64. Stage: 4 planes x 64 rows x 64 cols bf16 = 32KB; 3-stage ring.
#define STG_ELEMS 16384
#define PLANE     4096

// ---- generic single-source prefetch (pre_gemm path) ----
__device__ __forceinline__ void prefetch_single(
        const bf* __restrict__ Ahi, const bf* __restrict__ Alo, int lda_a,
        const bf* __restrict__ Whi, const bf* __restrict__ Wlo,
        int row0, int colbase, int kc, bf* stg) {
    const int r  = (threadIdx.x >> 2) & 63;
    const int cs = threadIdx.x & 3;
    const int wrow = ((r >> 4) << 9) + colbase + (r & 15);
    const int kbase = kc * 64;
    const bf* sa_hi = Ahi + (size_t)(row0 + r) * lda_a + kbase;
    const bf* sa_lo = Alo + (size_t)(row0 + r) * lda_a + kbase;
    const bf* sw_hi = Whi + (size_t)wrow * 512 + kbase;
    const bf* sw_lo = Wlo + (size_t)wrow * 512 + kbase;
#pragma unroll
    for (int u = 0; u < 2; u++) {
        int s = cs + u * 4;
        bf* d = stg + r * 64 + ((s ^ (r & 7)) * 8);
        cp16(d + 0 * PLANE, sa_hi + s * 8);
        cp16(d + 1 * PLANE, sa_lo + s * 8);
        cp16(d + 2 * PLANE, sw_hi + s * 8);
        cp16(d + 3 * PLANE, sw_lo + s * 8);
    }
}

// ---- wave prefetch: 5 K-segments (l0, l1-rec, l1-in, l2-rec, l2-in) ----
__device__ __forceinline__ void prefetch_wave(int op, int row0, int colbase,
                                              int kc, bf* stg) {
    const int seg = kc >> 3;
    const int kbase = (kc & 7) * 64;
    const int alayer = (seg == 0 || seg == 2) ? ((seg == 0) ? 0 : 0)
                     : (seg == 1 || seg == 4) ? 1 : 2;
    const bf* Ahi = &g_hhi[op][alayer][0];
    const bf* Alo = &g_hlo[op][alayer][0];
    const bf *Whi, *Wlo;
    switch (seg) {
        case 0:  Whi = g_whh_hi;           Wlo = g_whh_lo;           break;
        case 1:  Whi = g_whh_hi + GH;      Wlo = g_whh_lo + GH;      break;
        case 2:  Whi = g_wih_hi + GH;      Wlo = g_wih_lo + GH;      break;
        case 3:  Whi = g_whh_hi + 2 * GH;  Wlo = g_whh_lo + 2 * GH;  break;
        default: Whi = g_wih_hi + 2 * GH;  Wlo = g_wih_lo + 2 * GH;  break;
    }
    const int r  = (threadIdx.x >> 2) & 63;
    const int cs = threadIdx.x & 3;
    const int wrow = ((r >> 4) << 9) + colbase + (r & 15);
    const bf* sa_hi = Ahi + (size_t)(row0 + r) * H + kbase;
    const bf* sa_lo = Alo + (size_t)(row0 + r) * H + kbase;
    const bf* sw_hi = Whi + (size_t)wrow * 512 + kbase;
    const bf* sw_lo = Wlo + (size_t)wrow * 512 + kbase;
#pragma unroll
    for (int u = 0; u < 2; u++) {
        int s = cs + u * 4;
        bf* d = stg + r * 64 + ((s ^ (r & 7)) * 8);
        cp16(d + 0 * PLANE, sa_hi + s * 8);
        cp16(d + 1 * PLANE, sa_lo + s * 8);
        cp16(d + 2 * PLANE, sw_hi + s * 8);
        cp16(d + 3 * PLANE, sw_lo + s * 8);
    }
}

// ---- inner compute for one 64-K chunk (12 MMAs/sub x 4 subs) ----
__device__ __forceinline__ void chunk_compute(uint32_t sb, int arow, int ahalf,
                                              int nrl, int bhalf, float acc[4][4]) {
#pragma unroll
    for (int sub = 0; sub < 4; sub++) {
        uint32_t ahi[4], alo[4];
        int aseg = (sub * 2 + ahalf) ^ (arow & 7);
        uint32_t aoff = (uint32_t)((arow * 64 + aseg * 8) * 2);
        ldm4(sb + 0 * 8192 + aoff, ahi);
        ldm4(sb + 1 * 8192 + aoff, alo);
        uint32_t bh0[4], bl0[4], bh1[4], bl1[4];
        {
            int nr = nrl;
            int bseg = (sub * 2 + bhalf) ^ (nr & 7);
            uint32_t boff = (uint32_t)((nr * 64 + bseg * 8) * 2);
            ldm4(sb + 2 * 8192 + boff, bh0);
            ldm4(sb + 3 * 8192 + boff, bl0);
        }
        {
            int nr = nrl + 16;
            int bseg = (sub * 2 + bhalf) ^ (nr & 7);
            uint32_t boff = (uint32_t)((nr * 64 + bseg * 8) * 2);
            ldm4(sb + 2 * 8192 + boff, bh1);
            ldm4(sb + 3 * 8192 + boff, bl1);
        }
        mma16816(acc[0], ahi, bh0[0], bh0[1]);
        mma16816(acc[1], ahi, bh0[2], bh0[3]);
        mma16816(acc[2], ahi, bh1[0], bh1[1]);
        mma16816(acc[3], ahi, bh1[2], bh1[3]);
        mma16816(acc[0], ahi, bl0[0], bl0[1]);
        mma16816(acc[1], ahi, bl0[2], bl0[3]);
        mma16816(acc[2], ahi, bl1[0], bl1[1]);
        mma16816(acc[3], ahi, bl1[2], bl1[3]);
        mma16816(acc[0], alo, bh0[0], bh0[1]);
        mma16816(acc[1], alo, bh0[2], bh0[3]);
        mma16816(acc[2], alo, bh1[0], bh1[1]);
        mma16816(acc[3], alo, bh1[2], bh1[3]);
    }
}

__device__ __forceinline__ void acc_coord(int nt, int e, int& r, int& c) {
    const int lane = threadIdx.x & 31, warp = threadIdx.x >> 5;
    const int wr = warp >> 1, wc = warp & 1;
    r = wr * 16 + (lane >> 2) + ((e >> 1) ? 8 : 0);
    c = wc * 32 + nt * 8 + (lane & 3) * 2 + (e & 1);
}

// ---------------------------------------------------------------------------
__global__ void split_w_kernel(const float* __restrict__ wih,
                               const float* __restrict__ whh) {
    int idx = blockIdx.x * blockDim.x + threadIdx.x;
    if (idx >= NL * GH) return;
    float a = wih[idx];
    bf h1 = __float2bfloat16(a);
    g_wih_hi[idx] = h1;
    g_wih_lo[idx] = __float2bfloat16(a - __bfloat162float(h1));
    float b = whh[idx];
    bf h2 = __float2bfloat16(b);
    g_whh_hi[idx] = h2;
    g_whh_lo[idx] = __float2bfloat16(b - __bfloat162float(h2));
}

// ---------------------------------------------------------------------------
// attn[b,d] = softmax_d( sum_t x[b,t,d]*attn_w[2H+t] )  — time-invariant.
// ---------------------------------------------------------------------------
__global__ void attn_kernel(const float* __restrict__ x, const float* __restrict__ aw,
                            float* __restrict__ out) {
    __shared__ float saw[T1];
    __shared__ float red[512];
    int b = blockIdx.x, d = threadIdx.x;
    if (d < T1) saw[d] = aw[2 * H + d];
    __syncthreads();
    const float* xb = x + (size_t)b * T1 * D;
    float acc = 0.f;
    for (int t = 0; t < T1; t++) acc += xb[(size_t)t * D + d] * saw[t];
    red[d] = acc;
    __syncthreads();
    for (int s = 256; s > 0; s >>= 1) {
        if (d < s) red[d] = fmaxf(red[d], red[d + s]);
        __syncthreads();
    }
    float mx = red[0];
    __syncthreads();
    float e = expf(acc - mx);
    red[d] = e;
    __syncthreads();
    for (int s = 256; s > 0; s >>= 1) {
        if (d < s) red[d] += red[d + s];
        __syncthreads();
    }
    float a = e / red[0];
    float* ob = out + (size_t)b * T1 * D;
    for (int t = 0; t < T1; t++) {
        float w = a * xb[(size_t)t * D + d];
        ob[(size_t)t * D + d] = w;
        bf hi = __float2bfloat16(w);
        size_t gi = (size_t)b * T1 * D + (size_t)t * D + d;
        g_xhi[gi] = hi;
        g_xlo[gi] = __float2bfloat16(w - __bfloat162float(hi));
    }
}

// ---------------------------------------------------------------------------
// pre0 (remapped layout): pre0[t][b][tilec*64 + c] = weighted@Wih0^T + biases
// ---------------------------------------------------------------------------
__global__ void __launch_bounds__(NT) pre_gemm_kernel(const float* __restrict__ bih,
                                                      const float* __restrict__ bhh) {
    __shared__ __align__(16) bf smem[3 * STG_ELEMS];
    int tstep = blockIdx.x >> 2;
    int b0    = (blockIdx.x & 3) * 64;
    int tilec = blockIdx.y;
    int colbase = tilec * 16;
    const int lane = threadIdx.x & 31, warp = threadIdx.x >> 5;
    const int arow  = (warp >> 1) * 16 + (lane & 15);
    const int ahalf = lane >> 4;
    const int nrl   = (warp & 1) * 32 + ((lane >> 4) << 3) + (lane & 7);
    const int bhalf = (lane >> 3) & 1;
    const uint32_t sbase = (uint32_t)__cvta_generic_to_shared(smem);
    const bf* Ahi = g_xhi + (size_t)tstep * D;
    const bf* Alo = g_xlo + (size_t)tstep * D;

    float acc[4][4] = {};
    prefetch_single(Ahi, Alo, T1 * D, g_wih_hi, g_wih_lo, b0, colbase, 0, smem);
    CP_COMMIT();
    prefetch_single(Ahi, Alo, T1 * D, g_wih_hi, g_wih_lo, b0, colbase, 1, smem + STG_ELEMS);
    CP_COMMIT();
    for (int kc = 0; kc < 8; kc++) {
        CP_WAIT1();
        __syncthreads();
        if (kc + 2 < 8)
            prefetch_single(Ahi, Alo, T1 * D, g_wih_hi, g_wih_lo, b0, colbase,
                            kc + 2, smem + ((kc + 2) % 3) * STG_ELEMS);
        CP_COMMIT();
        chunk_compute(sbase + (uint32_t)((kc % 3) * STG_ELEMS * 2),
                      arow, ahalf, nrl, bhalf, acc);
    }
    __syncthreads();

    size_t base = (size_t)tstep * B * G;
#pragma unroll
    for (int nt = 0; nt < 4; nt++)
#pragma unroll
        for (int e = 0; e < 4; e++) {
            int r, c;
            acc_coord(nt, e, r, c);
            int bcol = ((c >> 4) << 9) + colbase + (c & 15);
            g_pre0[base + (size_t)(b0 + r) * G + tilec * 64 + c] =
                acc[nt][e] + bih[bcol] + bhh[bcol];
        }
}

// ---------------------------------------------------------------------------
// Persistent wavefront kernel: wave w computes l0@t=w, l1@t=w-1, l2@t=w-2.
// ONE fused 40-chunk GEMM (K=2560, 5 segments), ONE ew, ONE barrier per wave.
// All wave-w reads were written in wave w-1 -> parity double-buffer is safe.
// ---------------------------------------------------------------------------
__global__ void __launch_bounds__(NT, 1) lstm_kernel(const float* __restrict__ bih,
                                                     const float* __restrict__ bhh,
                                                     float* __restrict__ out) {
    __shared__ __align__(16) bf smem[3 * STG_ELEMS];    // 96KB ring
    __shared__ float sg[NL][64][65];                    // 3 gate tiles (~50KB)
    __shared__ float sc[NL][64 * 16];                   // cell state
    __shared__ float sbias[2][64];

    const int tile = blockIdx.x;
    const int row0    = (tile >> 5) * 64;
    const int tilec   = tile & 31;
    const int colbase = tilec * 16;
    const int tid = threadIdx.x;
    const int lane = tid & 31, warp = tid >> 5;
    const int arow  = (warp >> 1) * 16 + (lane & 15);
    const int ahalf = lane >> 4;
    const int nrl   = (warp & 1) * 32 + ((lane >> 4) << 3) + (lane & 7);
    const int bhalf = (lane >> 3) & 1;
    const uint32_t sbase = (uint32_t)__cvta_generic_to_shared(smem);

    unsigned gen = *(volatile unsigned*)&g_rel;

    // zero BOTH parities of h (out-of-range wave reads must see zeros)
    for (int idx = blockIdx.x * NT + tid; idx < 2 * NL * B * H; idx += GRID * NT) {
        ((bf*)g_hhi)[idx] = __float2bfloat16(0.f);
        ((bf*)g_hlo)[idx] = __float2bfloat16(0.f);
    }
    for (int k = tid; k < NL * 64 * 16; k += NT) ((float*)sc)[k] = 0.f;
    if (tid < 128) {
        int l = (tid >> 6) + 1, c = tid & 63;
        int bcol = l * G + ((c >> 4) << 9) + colbase + (c & 15);
        sbias[l - 1][c] = bih[bcol] + bhh[bcol];
    }
    gbar(++gen);

    for (int w = 0; w < T1 + 2; w++) {
        const int np = w & 1, op = np ^ 1;

        float acc0[4][4] = {}, acc1[4][4] = {}, acc2[4][4] = {};
        prefetch_wave(op, row0, colbase, 0, smem);
        CP_COMMIT();
        prefetch_wave(op, row0, colbase, 1, smem + STG_ELEMS);
        CP_COMMIT();
        for (int kc = 0; kc < 40; kc++) {
            CP_WAIT1();
            __syncthreads();
            if (kc + 2 < 40)
                prefetch_wave(op, row0, colbase, kc + 2,
                              smem + ((kc + 2) % 3) * STG_ELEMS);
            CP_COMMIT();
            const uint32_t sb = sbase + (uint32_t)((kc % 3) * STG_ELEMS * 2);
            if (kc < 8)       chunk_compute(sb, arow, ahalf, nrl, bhalf, acc0);
            else if (kc < 24) chunk_compute(sb, arow, ahalf, nrl, bhalf, acc1);
            else              chunk_compute(sb, arow, ahalf, nrl, bhalf, acc2);
        }
        __syncthreads();

        // stage all 3 gate tiles
#pragma unroll
        for (int nt = 0; nt < 4; nt++)
#pragma unroll
            for (int e = 0; e < 4; e++) {
                int r, c;
                acc_coord(nt, e, r, c);
                sg[0][r][c] = acc0[nt][e];
                sg[1][r][c] = acc1[nt][e];
                sg[2][r][c] = acc2[nt][e];
            }
        __syncthreads();

        // merged cell update: l0@t=w, l1@t=w-1, l2@t=w-2 (each guarded)
#pragma unroll
        for (int l = 0; l < NL; l++) {
            const int t = w - l;
            if (t < 0 || t >= T1) continue;
#pragma unroll
            for (int k = 0; k < 4; k++) {
                int idx = tid + k * NT;
                int b = idx >> 4, j = idx & 15;
                float gi = sg[l][b][j], gf = sg[l][b][16 + j],
                      gg = sg[l][b][32 + j], go = sg[l][b][48 + j];
                if (l == 0) {
                    const float* p = g_pre0 + (size_t)t * B * G
                                   + (size_t)(row0 + b) * G + tilec * 64;
                    gi += p[j]; gf += p[16 + j]; gg += p[32 + j]; go += p[48 + j];
                } else {
                    const float* sb2 = sbias[l - 1];
                    gi += sb2[j]; gf += sb2[16 + j]; gg += sb2[32 + j]; go += sb2[48 + j];
                }
                float i_ = sigm(gi), f_ = sigm(gf), g_ = tanhf(gg), o_ = sigm(go);
                float cn = f_ * sc[l][idx] + i_ * g_;
                float hn = o_ * tanhf(cn);
                sc[l][idx] = cn;
                bf hh = __float2bfloat16(hn);
                size_t hidx = (size_t)(row0 + b) * H + colbase + j;
                g_hhi[np][l][hidx] = hh;
                g_hlo[np][l][hidx] = __float2bfloat16(hn - __bfloat162float(hh));
                if (l == NL - 1)
                    out[OUT_ENC + (size_t)(row0 + b) * T1 * H + (size_t)t * H
                        + colbase + j] = hn;
            }
        }
        gbar(++gen);
    }
}

// ---------------------------------------------------------------------------
extern "C" void kernel_launch(void* const* d_in, const int* in_sizes, int n_in,
                              void* d_out, int out_size) {
    const float* x   = (const float*)d_in[0];
    const float* wih = (const float*)d_in[1];
    const float* whh = (const float*)d_in[2];
    const float* bih = (const float*)d_in[3];
    const float* bhh = (const float*)d_in[4];
    const float* aw  = (const float*)d_in[5];
    float* out = (float*)d_out;

    split_w_kernel<<<(NL * GH + 255) / 256, 256>>>(wih, whh);
    attn_kernel<<<B, 512>>>(x, aw, out);
    dim3 pgrid(T1 * 4, G / 64);
    pre_gemm_kernel<<<pgrid, NT>>>(bih, bhh);
    lstm_kernel<<<GRID, NT>>>(bih, bhh, out);
}

// round 10
// speedup vs baseline: 1.8347x; 1.7058x over previous
#include <cuda_runtime.h>
#include <cuda_fp16.h>
#include <math.h>
#include <stdint.h>

#define B   256
#define T1  127
#define D   512
#define H   512
#define G   2048
#define NL  3
#define GH  (G * H)
#define OUT_ENC ((size_t)B * T1 * D)

#define GRID 128
#define NT   256

typedef __half hf;

// ---------------------------------------------------------------------------
// Scratch
// ---------------------------------------------------------------------------
__device__ float g_pre0[(size_t)T1 * B * G];   // [t][b][tilec*64 + c] remapped
__device__ hf g_h[2][NL][B * H];               // wave-parity double buffer
__device__ hf g_wih[NL * GH];
__device__ hf g_whh[NL * GH];
__device__ hf g_x[(size_t)B * T1 * D];
__device__ unsigned g_flags[GRID];
__device__ unsigned g_rel;

// ---------------------------------------------------------------------------
// Flag-based grid barrier (per-CTA flag slots)
// ---------------------------------------------------------------------------
__device__ __forceinline__ void gbar(unsigned gen) {
    __syncthreads();
    if (threadIdx.x == 0) {
        __threadfence();
        ((volatile unsigned*)g_flags)[blockIdx.x] = gen;
    }
    if (blockIdx.x == 0) {
        if (threadIdx.x < GRID)
            while ((int)(((volatile unsigned*)g_flags)[threadIdx.x] - gen) < 0) {}
        __syncthreads();
        if (threadIdx.x == 0) {
            __threadfence();
            *(volatile unsigned*)&g_rel = gen;
        }
    }
    while ((int)(*(volatile unsigned*)&g_rel - gen) < 0) {}
    __threadfence();
    __syncthreads();
}

__device__ __forceinline__ float sigm(float x) { return 1.f / (1.f + expf(-x)); }

// ---------------------------------------------------------------------------
__device__ __forceinline__ void cp16u(uint32_t dst, const hf* src) {
    asm volatile("cp.async.cg.shared.global [%0], [%1], 16;" :: "r"(dst), "l"(src));
}
#define CP_COMMIT() asm volatile("cp.async.commit_group;" ::: "memory")
#define CP_WAIT1()  asm volatile("cp.async.wait_group 1;" ::: "memory")

__device__ __forceinline__ void ldm4(uint32_t addr, uint32_t r[4]) {
    asm volatile("ldmatrix.sync.aligned.m8n8.x4.shared.b16 {%0,%1,%2,%3}, [%4];"
                 : "=r"(r[0]), "=r"(r[1]), "=r"(r[2]), "=r"(r[3]) : "r"(addr));
}
__device__ __forceinline__ void mma16816(float c[4], const uint32_t a[4],
                                         uint32_t b0, uint32_t b1) {
    asm volatile(
        "mma.sync.aligned.m16n8k16.row.col.f32.f16.f16.f32 "
        "{%0,%1,%2,%3},{%4,%5,%6,%7},{%8,%9},{%0,%1,%2,%3};"
        : "+f"(c[0]), "+f"(c[1]), "+f"(c[2]), "+f"(c[3])
        : "r"(a[0]), "r"(a[1]), "r"(a[2]), "r"(a[3]), "r"(b0), "r"(b1));
}

// K-chunk = 64. Stage: A plane 8KB + B plane 8KB = 16KB; 3-stage ring (48KB).
#define STG_BYTES 16384
#define PLANE_B   8192

// Stage one 64-K chunk: A rows (64, lda) from A (pre-offset to row0/kb),
// B rows gathered: wrow = (r>>4)*512 + colbase + (r&15), W pre-offset by kb.
__device__ __forceinline__ void stage_chunk(const hf* __restrict__ A, int lda,
                                            const hf* __restrict__ W, int colbase,
                                            uint32_t st) {
    const int tid = threadIdx.x;
#pragma unroll
    for (int u = 0; u < 4; u++) {
        int id = tid + u * NT;              // 0..1023
        int pl = id >> 9, rm = id & 511;
        int r = rm >> 3, s = rm & 7;
        uint32_t dst = st + (uint32_t)(pl * PLANE_B + r * 128 + ((s ^ (r & 7)) * 16));
        const hf* sp;
        if (pl == 0) {
            sp = A + (size_t)r * lda + s * 8;
        } else {
            int wrow = ((r >> 4) << 9) + colbase + (r & 15);
            sp = W + (size_t)wrow * 512 + s * 8;
        }
        cp16u(dst, sp);
    }
}

// Single-pass fp16 chunk: 4 subs x (1 A-ldm4 + 2 B-ldm4 + 4 MMA)
__device__ __forceinline__ void chunk_compute(uint32_t sb, int arow, int ahalf,
                                              int nrl, int bhalf, float acc[4][4]) {
#pragma unroll
    for (int sub = 0; sub < 4; sub++) {
        uint32_t a[4];
        int aseg = (sub * 2 + ahalf) ^ (arow & 7);
        ldm4(sb + (uint32_t)(arow * 128 + aseg * 16), a);
        uint32_t b0[4], b1[4];
        {
            int nr = nrl;
            int bseg = (sub * 2 + bhalf) ^ (nr & 7);
            ldm4(sb + (uint32_t)(PLANE_B + nr * 128 + bseg * 16), b0);
        }
        {
            int nr = nrl + 16;
            int bseg = (sub * 2 + bhalf) ^ (nr & 7);
            ldm4(sb + (uint32_t)(PLANE_B + nr * 128 + bseg * 16), b1);
        }
        mma16816(acc[0], a, b0[0], b0[1]);
        mma16816(acc[1], a, b0[2], b0[3]);
        mma16816(acc[2], a, b1[0], b1[1]);
        mma16816(acc[3], a, b1[2], b1[3]);
    }
}

__device__ __forceinline__ void acc_coord(int nt, int e, int& r, int& c) {
    const int lane = threadIdx.x & 31, warp = threadIdx.x >> 5;
    const int wr = warp >> 1, wc = warp & 1;
    r = wr * 16 + (lane >> 2) + ((e >> 1) ? 8 : 0);
    c = wc * 32 + nt * 8 + (lane & 3) * 2 + (e & 1);
}

// ---------------------------------------------------------------------------
__global__ void split_w_kernel(const float* __restrict__ wih,
                               const float* __restrict__ whh) {
    int idx = blockIdx.x * blockDim.x + threadIdx.x;
    if (idx >= NL * GH) return;
    g_wih[idx] = __float2half(wih[idx]);
    g_whh[idx] = __float2half(whh[idx]);
}

// ---------------------------------------------------------------------------
// attn[b,d] = softmax_d( sum_t x[b,t,d]*attn_w[2H+t] )  — time-invariant.
// ---------------------------------------------------------------------------
__global__ void attn_kernel(const float* __restrict__ x, const float* __restrict__ aw,
                            float* __restrict__ out) {
    __shared__ float saw[T1];
    __shared__ float red[512];
    int b = blockIdx.x, d = threadIdx.x;
    if (d < T1) saw[d] = aw[2 * H + d];
    __syncthreads();
    const float* xb = x + (size_t)b * T1 * D;
    float acc = 0.f;
    for (int t = 0; t < T1; t++) acc += xb[(size_t)t * D + d] * saw[t];
    red[d] = acc;
    __syncthreads();
    for (int s = 256; s > 0; s >>= 1) {
        if (d < s) red[d] = fmaxf(red[d], red[d + s]);
        __syncthreads();
    }
    float mx = red[0];
    __syncthreads();
    float e = expf(acc - mx);
    red[d] = e;
    __syncthreads();
    for (int s = 256; s > 0; s >>= 1) {
        if (d < s) red[d] += red[d + s];
        __syncthreads();
    }
    float a = e / red[0];
    float* ob = out + (size_t)b * T1 * D;
    for (int t = 0; t < T1; t++) {
        float w = a * xb[(size_t)t * D + d];
        ob[(size_t)t * D + d] = w;
        g_x[(size_t)b * T1 * D + (size_t)t * D + d] = __float2half(w);
    }
}

// ---------------------------------------------------------------------------
// pre0: [t][b][tilec*64 + c] = weighted@Wih0^T + b_ih0 + b_hh0
// (c -> W row (c>>4)*512 + tilec*16 + (c&15))
// ---------------------------------------------------------------------------
__global__ void __launch_bounds__(NT) pre_gemm_kernel(const float* __restrict__ bih,
                                                      const float* __restrict__ bhh) {
    __shared__ __align__(128) char ring[3 * STG_BYTES];
    int tstep = blockIdx.x >> 2;
    int b0    = (blockIdx.x & 3) * 64;
    int tilec = blockIdx.y;
    int colbase = tilec * 16;
    const int lane = threadIdx.x & 31, warp = threadIdx.x >> 5;
    const int arow  = (warp >> 1) * 16 + (lane & 15);
    const int ahalf = lane >> 4;
    const int nrl   = (warp & 1) * 32 + ((lane >> 4) << 3) + (lane & 7);
    const int bhalf = (lane >> 3) & 1;
    const uint32_t sbase = (uint32_t)__cvta_generic_to_shared(ring);
    const hf* A0 = g_x + (size_t)tstep * D + (size_t)b0 * (T1 * D);

    float acc[4][4] = {};
    stage_chunk(A0, T1 * D, g_wih, colbase, sbase);
    CP_COMMIT();
    stage_chunk(A0 + 64, T1 * D, g_wih + 64, colbase, sbase + STG_BYTES);
    CP_COMMIT();
    for (int kc = 0; kc < 8; kc++) {
        CP_WAIT1();
        __syncthreads();
        if (kc + 2 < 8)
            stage_chunk(A0 + (kc + 2) * 64, T1 * D, g_wih + (kc + 2) * 64, colbase,
                        sbase + ((kc + 2) % 3) * STG_BYTES);
        CP_COMMIT();
        chunk_compute(sbase + (uint32_t)((kc % 3) * STG_BYTES),
                      arow, ahalf, nrl, bhalf, acc);
    }
    __syncthreads();

    size_t base = (size_t)tstep * B * G;
#pragma unroll
    for (int nt = 0; nt < 4; nt++)
#pragma unroll
        for (int e = 0; e < 4; e++) {
            int r, c;
            acc_coord(nt, e, r, c);
            int bcol = ((c >> 4) << 9) + colbase + (c & 15);
            g_pre0[base + (size_t)(b0 + r) * G + tilec * 64 + c] =
                acc[nt][e] + bih[bcol] + bhh[bcol];
        }
}

// ---------------------------------------------------------------------------
// Persistent wavefront kernel: wave w computes l0@t=w, l1@t=w-1, l2@t=w-2.
// One fused 40-chunk GEMM (K=2560, 5 segments), one ew, one barrier per wave.
// ---------------------------------------------------------------------------
#define NCH 40

__global__ void __launch_bounds__(NT, 1) lstm_kernel(const float* __restrict__ bih,
                                                     const float* __restrict__ bhh,
                                                     float* __restrict__ out) {
    __shared__ __align__(128) char ring[3 * STG_BYTES];   // 48KB
    __shared__ float sg[NL][64][65];                      // gate tiles (~50KB)
    __shared__ float sc[NL][64 * 16];                     // cell state
    __shared__ float sbias[2][64];

    const int tile = blockIdx.x;
    const int row0    = (tile >> 5) * 64;
    const int tilec   = tile & 31;
    const int colbase = tilec * 16;
    const int tid = threadIdx.x;
    const int lane = tid & 31, warp = tid >> 5;
    const int arow  = (warp >> 1) * 16 + (lane & 15);
    const int ahalf = lane >> 4;
    const int nrl   = (warp & 1) * 32 + ((lane >> 4) << 3) + (lane & 7);
    const int bhalf = (lane >> 3) & 1;
    const uint32_t sbase = (uint32_t)__cvta_generic_to_shared(ring);

    unsigned gen = *(volatile unsigned*)&g_rel;

    // zero both h parities (boundary waves read zeros)
    for (int idx = blockIdx.x * NT + tid; idx < 2 * NL * B * H; idx += GRID * NT)
        ((hf*)g_h)[idx] = __float2half(0.f);
    for (int k = tid; k < NL * 64 * 16; k += NT) ((float*)sc)[k] = 0.f;
    if (tid < 128) {
        int l = (tid >> 6) + 1, c = tid & 63;
        int bcol = l * G + ((c >> 4) << 9) + colbase + (c & 15);
        sbias[l - 1][c] = bih[bcol] + bhh[bcol];
    }
    gbar(++gen);

    for (int w = 0; w < T1 + 2; w++) {
        const int np = w & 1, op = np ^ 1;

        // seg: 0=Whh0(h0) 1=Whh1(h1) 2=Wih1(h0) 3=Whh2(h2) 4=Wih2(h1)
        const hf* asrc[5] = { g_h[op][0], g_h[op][1], g_h[op][0],
                              g_h[op][2], g_h[op][1] };
        const hf* wsrc[5] = { g_whh, g_whh + GH, g_wih + GH,
                              g_whh + 2 * GH, g_wih + 2 * GH };

        auto stage_wave = [&](int kc) {
            int seg = kc >> 3, kb = (kc & 7) * 64;
            stage_chunk(asrc[seg] + (size_t)row0 * H + kb, H,
                        wsrc[seg] + kb, colbase,
                        sbase + (uint32_t)((kc % 3) * STG_BYTES));
        };

        float acc0[4][4] = {}, acc1[4][4] = {}, acc2[4][4] = {};
        stage_wave(0);
        CP_COMMIT();
        stage_wave(1);
        CP_COMMIT();
        for (int kc = 0; kc < NCH; kc++) {
            CP_WAIT1();
            __syncthreads();
            if (kc + 2 < NCH) stage_wave(kc + 2);
            CP_COMMIT();
            const uint32_t sb = sbase + (uint32_t)((kc % 3) * STG_BYTES);
            if (kc < 8)       chunk_compute(sb, arow, ahalf, nrl, bhalf, acc0);
            else if (kc < 24) chunk_compute(sb, arow, ahalf, nrl, bhalf, acc1);
            else              chunk_compute(sb, arow, ahalf, nrl, bhalf, acc2);
        }
        __syncthreads();

#pragma unroll
        for (int nt = 0; nt < 4; nt++)
#pragma unroll
            for (int e = 0; e < 4; e++) {
                int r, c;
                acc_coord(nt, e, r, c);
                sg[0][r][c] = acc0[nt][e];
                sg[1][r][c] = acc1[nt][e];
                sg[2][r][c] = acc2[nt][e];
            }
        __syncthreads();

        // merged cell update: l0@t=w, l1@t=w-1, l2@t=w-2
#pragma unroll
        for (int l = 0; l < NL; l++) {
            const int t = w - l;
            if (t < 0 || t >= T1) continue;
#pragma unroll
            for (int k = 0; k < 4; k++) {
                int idx = tid + k * NT;
                int b = idx >> 4, j = idx & 15;
                float gi = sg[l][b][j], gf = sg[l][b][16 + j],
                      gg = sg[l][b][32 + j], go = sg[l][b][48 + j];
                if (l == 0) {
                    const float* p = g_pre0 + (size_t)t * B * G
                                   + (size_t)(row0 + b) * G + tilec * 64;
                    gi += p[j]; gf += p[16 + j]; gg += p[32 + j]; go += p[48 + j];
                } else {
                    const float* sb2 = sbias[l - 1];
                    gi += sb2[j]; gf += sb2[16 + j]; gg += sb2[32 + j]; go += sb2[48 + j];
                }
                float i_ = sigm(gi), f_ = sigm(gf), g_ = tanhf(gg), o_ = sigm(go);
                float cn = f_ * sc[l][idx] + i_ * g_;
                float hn = o_ * tanhf(cn);
                sc[l][idx] = cn;
                g_h[np][l][(size_t)(row0 + b) * H + colbase + j] = __float2half(hn);
                if (l == NL - 1)
                    out[OUT_ENC + (size_t)(row0 + b) * T1 * H + (size_t)t * H
                        + colbase + j] = hn;
            }
        }
        gbar(++gen);
    }
}

// ---------------------------------------------------------------------------
extern "C" void kernel_launch(void* const* d_in, const int* in_sizes, int n_in,
                              void* d_out, int out_size) {
    const float* x   = (const float*)d_in[0];
    const float* wih = (const float*)d_in[1];
    const float* whh = (const float*)d_in[2];
    const float* bih = (const float*)d_in[3];
    const float* bhh = (const float*)d_in[4];
    const float* aw  = (const float*)d_in[5];
    float* out = (float*)d_out;

    split_w_kernel<<<(NL * GH + 255) / 256, 256>>>(wih, whh);
    attn_kernel<<<B, 512>>>(x, aw, out);
    dim3 pgrid(T1 * 4, G / 64);
    pre_gemm_kernel<<<pgrid, NT>>>(bih, bhh);
    lstm_kernel<<<GRID, NT>>>(bih, bhh, out);
}

// round 11
// speedup vs baseline: 2.6032x; 1.4189x over previous
#include <cuda_runtime.h>
#include <cuda_fp16.h>
#include <math.h>
#include <stdint.h>

#define B   256
#define T1  127
#define D   512
#define H   512
#define G   2048
#define NL  3
#define GH  (G * H)
#define OUT_ENC ((size_t)B * T1 * D)

#define GRID 128
#define NT   256

typedef __half hf;

// ---------------------------------------------------------------------------
// Scratch
// ---------------------------------------------------------------------------
__device__ float g_pre0[(size_t)T1 * B * G];   // [t][b][tilen*32 + q*8 + j]
__device__ hf g_h[2][NL][B * H];               // wave-parity double buffer
__device__ hf g_wih[NL * GH];
__device__ hf g_whh[NL * GH];
__device__ hf g_x[(size_t)B * T1 * D];
__device__ unsigned g_flags[GRID];
__device__ unsigned g_rel;

// ---------------------------------------------------------------------------
// Flag-based grid barrier (per-CTA flag slots)
// ---------------------------------------------------------------------------
__device__ __forceinline__ void gbar(unsigned gen) {
    __syncthreads();
    if (threadIdx.x == 0) {
        __threadfence();
        ((volatile unsigned*)g_flags)[blockIdx.x] = gen;
    }
    if (blockIdx.x == 0) {
        if (threadIdx.x < GRID)
            while ((int)(((volatile unsigned*)g_flags)[threadIdx.x] - gen) < 0) {}
        __syncthreads();
        if (threadIdx.x == 0) {
            __threadfence();
            *(volatile unsigned*)&g_rel = gen;
        }
    }
    while ((int)(*(volatile unsigned*)&g_rel - gen) < 0) {}
    __threadfence();
    __syncthreads();
}

__device__ __forceinline__ float sigm(float x) { return 1.f / (1.f + expf(-x)); }

// ---------------------------------------------------------------------------
__device__ __forceinline__ void cp16u(uint32_t dst, const hf* src) {
    asm volatile("cp.async.cg.shared.global [%0], [%1], 16;" :: "r"(dst), "l"(src));
}
#define CP_COMMIT()  asm volatile("cp.async.commit_group;" ::: "memory")
#define CP_WAIT1()   asm volatile("cp.async.wait_group 1;" ::: "memory")
#define CP_WAITALL() asm volatile("cp.async.wait_group 0;" ::: "memory")

__device__ __forceinline__ void ldm4(uint32_t addr, uint32_t r[4]) {
    asm volatile("ldmatrix.sync.aligned.m8n8.x4.shared.b16 {%0,%1,%2,%3}, [%4];"
                 : "=r"(r[0]), "=r"(r[1]), "=r"(r[2]), "=r"(r[3]) : "r"(addr));
}
__device__ __forceinline__ void mma16816(float c[4], const uint32_t a[4],
                                         uint32_t b0, uint32_t b1) {
    asm volatile(
        "mma.sync.aligned.m16n8k16.row.col.f32.f16.f16.f32 "
        "{%0,%1,%2,%3},{%4,%5,%6,%7},{%8,%9},{%0,%1,%2,%3};"
        : "+f"(c[0]), "+f"(c[1]), "+f"(c[2]), "+f"(c[3])
        : "r"(a[0]), "r"(a[1]), "r"(a[2]), "r"(a[3]), "r"(b0), "r"(b1));
}

// ---------------------------------------------------------------------------
// pre_gemm (64x64 tile, streams A+B) — unchanged machinery from R10
// ---------------------------------------------------------------------------
#define STG_BYTES 16384
#define PLANE_B   8192

__device__ __forceinline__ void stage_chunk(const hf* __restrict__ A, int lda,
                                            const hf* __restrict__ W, int colbase,
                                            uint32_t st) {
    const int tid = threadIdx.x;
#pragma unroll
    for (int u = 0; u < 4; u++) {
        int id = tid + u * NT;
        int pl = id >> 9, rm = id & 511;
        int r = rm >> 3, s = rm & 7;
        uint32_t dst = st + (uint32_t)(pl * PLANE_B + r * 128 + ((s ^ (r & 7)) * 16));
        const hf* sp;
        if (pl == 0) {
            sp = A + (size_t)r * lda + s * 8;
        } else {
            int wrow = ((r >> 4) << 9) + colbase + (r & 15);
            sp = W + (size_t)wrow * 512 + s * 8;
        }
        cp16u(dst, sp);
    }
}

__device__ __forceinline__ void chunk_compute64(uint32_t sb, int arow, int ahalf,
                                                int nrl, int bhalf, float acc[4][4]) {
#pragma unroll
    for (int sub = 0; sub < 4; sub++) {
        uint32_t a[4];
        int aseg = (sub * 2 + ahalf) ^ (arow & 7);
        ldm4(sb + (uint32_t)(arow * 128 + aseg * 16), a);
        uint32_t b0[4], b1[4];
        {
            int nr = nrl;
            int bseg = (sub * 2 + bhalf) ^ (nr & 7);
            ldm4(sb + (uint32_t)(PLANE_B + nr * 128 + bseg * 16), b0);
        }
        {
            int nr = nrl + 16;
            int bseg = (sub * 2 + bhalf) ^ (nr & 7);
            ldm4(sb + (uint32_t)(PLANE_B + nr * 128 + bseg * 16), b1);
        }
        mma16816(acc[0], a, b0[0], b0[1]);
        mma16816(acc[1], a, b0[2], b0[3]);
        mma16816(acc[2], a, b1[0], b1[1]);
        mma16816(acc[3], a, b1[2], b1[3]);
    }
}

// ---------------------------------------------------------------------------
__global__ void split_w_kernel(const float* __restrict__ wih,
                               const float* __restrict__ whh) {
    int idx = blockIdx.x * blockDim.x + threadIdx.x;
    if (idx >= NL * GH) return;
    g_wih[idx] = __float2half(wih[idx]);
    g_whh[idx] = __float2half(whh[idx]);
}

// ---------------------------------------------------------------------------
// attn[b,d] = softmax_d( sum_t x[b,t,d]*attn_w[2H+t] )  — time-invariant.
// ---------------------------------------------------------------------------
__global__ void attn_kernel(const float* __restrict__ x, const float* __restrict__ aw,
                            float* __restrict__ out) {
    __shared__ float saw[T1];
    __shared__ float red[512];
    int b = blockIdx.x, d = threadIdx.x;
    if (d < T1) saw[d] = aw[2 * H + d];
    __syncthreads();
    const float* xb = x + (size_t)b * T1 * D;
    float acc = 0.f;
    for (int t = 0; t < T1; t++) acc += xb[(size_t)t * D + d] * saw[t];
    red[d] = acc;
    __syncthreads();
    for (int s = 256; s > 0; s >>= 1) {
        if (d < s) red[d] = fmaxf(red[d], red[d + s]);
        __syncthreads();
    }
    float mx = red[0];
    __syncthreads();
    float e = expf(acc - mx);
    red[d] = e;
    __syncthreads();
    for (int s = 256; s > 0; s >>= 1) {
        if (d < s) red[d] += red[d + s];
        __syncthreads();
    }
    float a = e / red[0];
    float* ob = out + (size_t)b * T1 * D;
    for (int t = 0; t < T1; t++) {
        float w = a * xb[(size_t)t * D + d];
        ob[(size_t)t * D + d] = w;
        g_x[(size_t)b * T1 * D + (size_t)t * D + d] = __float2half(w);
    }
}

// ---------------------------------------------------------------------------
// pre0: [t][b][tilen*32 + q*8 + j] = weighted@Wih0^T + b_ih0 + b_hh0
// (written from 64-wide tiles; tilen = tilec*2 + bit3(c))
// ---------------------------------------------------------------------------
__global__ void __launch_bounds__(NT) pre_gemm_kernel(const float* __restrict__ bih,
                                                      const float* __restrict__ bhh) {
    __shared__ __align__(128) char ring[3 * STG_BYTES];
    int tstep = blockIdx.x >> 2;
    int b0    = (blockIdx.x & 3) * 64;
    int tilec = blockIdx.y;
    int colbase = tilec * 16;
    const int lane = threadIdx.x & 31, warp = threadIdx.x >> 5;
    const int arow  = (warp >> 1) * 16 + (lane & 15);
    const int ahalf = lane >> 4;
    const int nrl   = (warp & 1) * 32 + ((lane >> 4) << 3) + (lane & 7);
    const int bhalf = (lane >> 3) & 1;
    const uint32_t sbase = (uint32_t)__cvta_generic_to_shared(ring);
    const hf* A0 = g_x + (size_t)tstep * D + (size_t)b0 * (T1 * D);

    float acc[4][4] = {};
    stage_chunk(A0, T1 * D, g_wih, colbase, sbase);
    CP_COMMIT();
    stage_chunk(A0 + 64, T1 * D, g_wih + 64, colbase, sbase + STG_BYTES);
    CP_COMMIT();
    for (int kc = 0; kc < 8; kc++) {
        CP_WAIT1();
        __syncthreads();
        if (kc + 2 < 8)
            stage_chunk(A0 + (kc + 2) * 64, T1 * D, g_wih + (kc + 2) * 64, colbase,
                        sbase + ((kc + 2) % 3) * STG_BYTES);
        CP_COMMIT();
        chunk_compute64(sbase + (uint32_t)((kc % 3) * STG_BYTES),
                        arow, ahalf, nrl, bhalf, acc);
    }
    __syncthreads();

    size_t base = (size_t)tstep * B * G;
#pragma unroll
    for (int nt = 0; nt < 4; nt++)
#pragma unroll
        for (int e = 0; e < 4; e++) {
            int r = (warp >> 1) * 16 + (lane >> 2) + ((e >> 1) ? 8 : 0);
            int c = (warp & 1) * 32 + nt * 8 + (lane & 3) * 2 + (e & 1);
            int bcol = ((c >> 4) << 9) + colbase + (c & 15);
            int idx = (tilec * 2 + ((c >> 3) & 1)) * 32 + ((c >> 4) << 3) + (c & 7);
            g_pre0[base + (size_t)(b0 + r) * G + idx] =
                acc[nt][e] + bih[bcol] + bhh[bcol];
        }
}

// ---------------------------------------------------------------------------
// Persistent wavefront kernel — M=128 x N=32 tiles, weights persistent in
// SMEM (160KB), A-only 3-stage ring (48KB), register-resident ew/cell state.
// Wave w computes l0@t=w, l1@t=w-1, l2@t=w-2; one barrier per wave.
// ---------------------------------------------------------------------------
#define NCH    40
#define WSEG_B 32768
#define ASTG_B 16384

__global__ void __launch_bounds__(NT, 1) lstm_kernel(const float* __restrict__ bih,
                                                     const float* __restrict__ bhh,
                                                     float* __restrict__ out) {
    __shared__ __align__(128) char wsm[5 * WSEG_B];    // 160KB persistent weights
    __shared__ __align__(128) char ring[3 * ASTG_B];   // 48KB A ring
    __shared__ float sbias[2][32];

    const int tid = threadIdx.x;
    const int warp = tid >> 5, lane = tid & 31;
    const int m     = blockIdx.x >> 6;        // 0..1
    const int tilen = blockIdx.x & 63;        // 0..63
    const int row0    = m * 128;
    const int colbase = tilen * 8;
    const int arow  = warp * 16 + (lane & 15);
    const int ahalf = lane >> 4;
    const int nrl   = ((lane >> 4) << 3) + (lane & 7);
    const int bhalf = (lane >> 3) & 1;
    const uint32_t wbase = (uint32_t)__cvta_generic_to_shared(wsm);
    const uint32_t rbase = (uint32_t)__cvta_generic_to_shared(ring);

    unsigned gen = *(volatile unsigned*)&g_rel;

    // zero both h parities (boundary waves read zeros)
    for (int idx = blockIdx.x * NT + tid; idx < 2 * NL * B * H; idx += GRID * NT)
        ((hf*)g_h)[idx] = __float2half(0.f);
    if (tid < 64) {
        int l = tid >> 5, c = tid & 31;
        int bcol = (l + 1) * G + ((c >> 3) << 9) + colbase + (c & 7);
        sbias[l][c] = bih[bcol] + bhh[bcol];
    }

    // one-time persistent weight load (gathered rows for this CTA's 32 cols)
    // seg: 0=Whh0 1=Whh1 2=Wih1 3=Whh2 4=Wih2 ; layout [seg][kchunk8][32r][64k]
    {
        const hf* wsrc[5] = { g_whh, g_whh + GH, g_wih + GH,
                              g_whh + 2 * GH, g_wih + 2 * GH };
#pragma unroll
        for (int it = 0; it < 40; it++) {
            int id = tid + it * NT;          // 0..10239
            int s   = id >> 11;
            int rem = id & 2047;
            int c = rem >> 8;
            int r = (rem >> 3) & 31;
            int k = rem & 7;
            int wrow = ((r >> 3) << 9) + colbase + (r & 7);
            uint32_t dst = wbase + (uint32_t)(s * WSEG_B + c * 4096 + r * 128
                          + ((k ^ (r & 7)) * 16));
            cp16u(dst, wsrc[s] + (size_t)wrow * 512 + c * 64 + k * 8);
        }
        CP_COMMIT();
        CP_WAITALL();
        __syncthreads();
    }

    float cst[NL][4];
#pragma unroll
    for (int l = 0; l < NL; l++)
#pragma unroll
        for (int e = 0; e < 4; e++) cst[l][e] = 0.f;

    const int rb = warp * 16 + (lane >> 2);
    const int j0 = (lane & 3) * 2;

    gbar(++gen);

    for (int w = 0; w < T1 + 2; w++) {
        const int np = w & 1, op = np ^ 1;
        const hf* asrc[5] = { g_h[op][0], g_h[op][1], g_h[op][0],
                              g_h[op][2], g_h[op][1] };

        auto stageA = [&](int kc) {
            int seg = kc >> 3, kb = (kc & 7) * 64;
            const hf* src = asrc[seg] + (size_t)row0 * H + kb;
            uint32_t st = rbase + (uint32_t)((kc % 3) * ASTG_B);
#pragma unroll
            for (int u = 0; u < 4; u++) {
                int id = tid + u * NT;         // 0..1023
                int r = id >> 3, k = id & 7;
                cp16u(st + (uint32_t)(r * 128 + ((k ^ (r & 7)) * 16)),
                      src + (size_t)r * H + k * 8);
            }
        };
        auto body = [&](int kc, float (&acc)[4][4]) {
            CP_WAIT1();
            __syncthreads();
            if (kc + 2 < NCH) stageA(kc + 2);
            CP_COMMIT();
            uint32_t sbA = rbase + (uint32_t)((kc % 3) * ASTG_B);
            uint32_t sbB = wbase + (uint32_t)((kc >> 3) * WSEG_B + (kc & 7) * 4096);
#pragma unroll
            for (int sub = 0; sub < 4; sub++) {
                uint32_t a[4];
                int aseg = (sub * 2 + ahalf) ^ (arow & 7);
                ldm4(sbA + (uint32_t)(arow * 128 + aseg * 16), a);
                uint32_t b0[4], b1[4];
                {
                    int nr = nrl;
                    int bseg = (sub * 2 + bhalf) ^ (nr & 7);
                    ldm4(sbB + (uint32_t)(nr * 128 + bseg * 16), b0);
                }
                {
                    int nr = nrl + 16;
                    int bseg = (sub * 2 + bhalf) ^ (nr & 7);
                    ldm4(sbB + (uint32_t)(nr * 128 + bseg * 16), b1);
                }
                mma16816(acc[0], a, b0[0], b0[1]);
                mma16816(acc[1], a, b0[2], b0[3]);
                mma16816(acc[2], a, b1[0], b1[1]);
                mma16816(acc[3], a, b1[2], b1[3]);
            }
        };

        float acc0[4][4] = {}, acc1[4][4] = {}, acc2[4][4] = {};
        stageA(0);
        CP_COMMIT();
        stageA(1);
        CP_COMMIT();
        for (int kc = 0; kc < 8; kc++)   body(kc, acc0);
        for (int kc = 8; kc < 24; kc++)  body(kc, acc1);
        for (int kc = 24; kc < 40; kc++) body(kc, acc2);

        // register-resident cell update: l0@t=w, l1@t=w-1, l2@t=w-2
#pragma unroll
        for (int l = 0; l < NL; l++) {
            const int t = w - l;
            if (t < 0 || t >= T1) continue;
            float (&A)[4][4] = (l == 0) ? acc0 : (l == 1) ? acc1 : acc2;
            float add[4][2][2];   // [gate][er][ej]
            if (l == 0) {
                const float* p = g_pre0 + (size_t)t * B * G + tilen * 32;
#pragma unroll
                for (int er = 0; er < 2; er++) {
                    const float* pr = p + (size_t)(row0 + rb + er * 8) * G;
#pragma unroll
                    for (int q = 0; q < 4; q++) {
                        float2 v = *(const float2*)(pr + q * 8 + j0);
                        add[q][er][0] = v.x;
                        add[q][er][1] = v.y;
                    }
                }
            } else {
#pragma unroll
                for (int q = 0; q < 4; q++) {
                    float v0 = sbias[l - 1][q * 8 + j0];
                    float v1 = sbias[l - 1][q * 8 + j0 + 1];
                    add[q][0][0] = add[q][1][0] = v0;
                    add[q][0][1] = add[q][1][1] = v1;
                }
            }
#pragma unroll
            for (int er = 0; er < 2; er++) {
                hf h2v[2];
                float hnf[2];
#pragma unroll
                for (int ej = 0; ej < 2; ej++) {
                    int e = er * 2 + ej;
                    float gi = A[0][e] + add[0][er][ej];
                    float gf = A[1][e] + add[1][er][ej];
                    float gg = A[2][e] + add[2][er][ej];
                    float go = A[3][e] + add[3][er][ej];
                    float i_ = sigm(gi), f_ = sigm(gf);
                    float g_ = tanhf(gg), o_ = sigm(go);
                    float cn = f_ * cst[l][e] + i_ * g_;
                    float hn = o_ * tanhf(cn);
                    cst[l][e] = cn;
                    h2v[ej] = __float2half(hn);
                    hnf[ej] = hn;
                }
                int row = row0 + rb + er * 8;
                *(__half2*)&g_h[np][l][(size_t)row * H + colbase + j0] =
                    *(__half2*)h2v;
                if (l == NL - 1)
                    *(float2*)(out + OUT_ENC + (size_t)row * T1 * H
                               + (size_t)t * H + colbase + j0) =
                        make_float2(hnf[0], hnf[1]);
            }
        }
        gbar(++gen);
    }
}

// ---------------------------------------------------------------------------
extern "C" void kernel_launch(void* const* d_in, const int* in_sizes, int n_in,
                              void* d_out, int out_size) {
    const float* x   = (const float*)d_in[0];
    const float* wih = (const float*)d_in[1];
    const float* whh = (const float*)d_in[2];
    const float* bih = (const float*)d_in[3];
    const float* bhh = (const float*)d_in[4];
    const float* aw  = (const float*)d_in[5];
    float* out = (float*)d_out;

    split_w_kernel<<<(NL * GH + 255) / 256, 256>>>(wih, whh);
    attn_kernel<<<B, 512>>>(x, aw, out);
    dim3 pgrid(T1 * 4, G / 64);
    pre_gemm_kernel<<<pgrid, NT>>>(bih, bhh);
    lstm_kernel<<<GRID, NT>>>(bih, bhh, out);
}

// round 12
// speedup vs baseline: 3.0980x; 1.1901x over previous
#include <cuda_runtime.h>
#include <cuda_fp16.h>
#include <math.h>
#include <stdint.h>

#define B   256
#define T1  127
#define D   512
#define H   512
#define G   2048
#define NL  3
#define GH  (G * H)
#define OUT_ENC ((size_t)B * T1 * D)

#define GRID 128
#define NT   256

typedef __half hf;

// ---------------------------------------------------------------------------
// Scratch
// ---------------------------------------------------------------------------
__device__ float g_pre0[(size_t)T1 * B * G];   // [t][b][tilen*32 + q*8 + j]
__device__ hf g_h[2][NL][B * H];               // wave-parity double buffer
__device__ hf g_wih[NL * GH];
__device__ hf g_whh[NL * GH];
__device__ hf g_x[(size_t)B * T1 * D];
__device__ unsigned g_flags[GRID];
__device__ unsigned g_rel;

// ---------------------------------------------------------------------------
// Flag-based grid barrier (per-CTA flag slots)
// ---------------------------------------------------------------------------
__device__ __forceinline__ void gbar(unsigned gen) {
    __syncthreads();
    if (threadIdx.x == 0) {
        __threadfence();
        ((volatile unsigned*)g_flags)[blockIdx.x] = gen;
    }
    if (blockIdx.x == 0) {
        if (threadIdx.x < GRID)
            while ((int)(((volatile unsigned*)g_flags)[threadIdx.x] - gen) < 0) {}
        __syncthreads();
        if (threadIdx.x == 0) {
            __threadfence();
            *(volatile unsigned*)&g_rel = gen;
        }
    }
    while ((int)(*(volatile unsigned*)&g_rel - gen) < 0) {}
    __threadfence();
    __syncthreads();
}

__device__ __forceinline__ float sigm(float x) { return 1.f / (1.f + expf(-x)); }

// ---------------------------------------------------------------------------
__device__ __forceinline__ void cp16u(uint32_t dst, const hf* src) {
    asm volatile("cp.async.cg.shared.global [%0], [%1], 16;" :: "r"(dst), "l"(src));
}
#define CP_COMMIT()  asm volatile("cp.async.commit_group;" ::: "memory")
#define CP_WAIT1()   asm volatile("cp.async.wait_group 1;" ::: "memory")
#define CP_WAITALL() asm volatile("cp.async.wait_group 0;" ::: "memory")

__device__ __forceinline__ void ldm4(uint32_t addr, uint32_t r[4]) {
    asm volatile("ldmatrix.sync.aligned.m8n8.x4.shared.b16 {%0,%1,%2,%3}, [%4];"
                 : "=r"(r[0]), "=r"(r[1]), "=r"(r[2]), "=r"(r[3]) : "r"(addr));
}
__device__ __forceinline__ void mma16816(float c[4], const uint32_t a[4],
                                         uint32_t b0, uint32_t b1) {
    asm volatile(
        "mma.sync.aligned.m16n8k16.row.col.f32.f16.f16.f32 "
        "{%0,%1,%2,%3},{%4,%5,%6,%7},{%8,%9},{%0,%1,%2,%3};"
        : "+f"(c[0]), "+f"(c[1]), "+f"(c[2]), "+f"(c[3])
        : "r"(a[0]), "r"(a[1]), "r"(a[2]), "r"(a[3]), "r"(b0), "r"(b1));
}

// ---------------------------------------------------------------------------
// pre_gemm (64x64 tile, streams A+B)
// ---------------------------------------------------------------------------
#define STG_BYTES 16384
#define PLANE_B   8192

__device__ __forceinline__ void stage_chunk(const hf* __restrict__ A, int lda,
                                            const hf* __restrict__ W, int colbase,
                                            uint32_t st) {
    const int tid = threadIdx.x;
#pragma unroll
    for (int u = 0; u < 4; u++) {
        int id = tid + u * NT;
        int pl = id >> 9, rm = id & 511;
        int r = rm >> 3, s = rm & 7;
        uint32_t dst = st + (uint32_t)(pl * PLANE_B + r * 128 + ((s ^ (r & 7)) * 16));
        const hf* sp;
        if (pl == 0) {
            sp = A + (size_t)r * lda + s * 8;
        } else {
            int wrow = ((r >> 4) << 9) + colbase + (r & 15);
            sp = W + (size_t)wrow * 512 + s * 8;
        }
        cp16u(dst, sp);
    }
}

__device__ __forceinline__ void chunk_compute64(uint32_t sb, int arow, int ahalf,
                                                int nrl, int bhalf, float acc[4][4]) {
#pragma unroll
    for (int sub = 0; sub < 4; sub++) {
        uint32_t a[4];
        int aseg = (sub * 2 + ahalf) ^ (arow & 7);
        ldm4(sb + (uint32_t)(arow * 128 + aseg * 16), a);
        uint32_t b0[4], b1[4];
        {
            int nr = nrl;
            int bseg = (sub * 2 + bhalf) ^ (nr & 7);
            ldm4(sb + (uint32_t)(PLANE_B + nr * 128 + bseg * 16), b0);
        }
        {
            int nr = nrl + 16;
            int bseg = (sub * 2 + bhalf) ^ (nr & 7);
            ldm4(sb + (uint32_t)(PLANE_B + nr * 128 + bseg * 16), b1);
        }
        mma16816(acc[0], a, b0[0], b0[1]);
        mma16816(acc[1], a, b0[2], b0[3]);
        mma16816(acc[2], a, b1[0], b1[1]);
        mma16816(acc[3], a, b1[2], b1[3]);
    }
}

// ---------------------------------------------------------------------------
__global__ void split_w_kernel(const float* __restrict__ wih,
                               const float* __restrict__ whh) {
    int idx = blockIdx.x * blockDim.x + threadIdx.x;
    if (idx >= NL * GH) return;
    g_wih[idx] = __float2half(wih[idx]);
    g_whh[idx] = __float2half(whh[idx]);
}

// ---------------------------------------------------------------------------
// attn[b,d] = softmax_d( sum_t x[b,t,d]*attn_w[2H+t] )  — time-invariant.
// ---------------------------------------------------------------------------
__global__ void attn_kernel(const float* __restrict__ x, const float* __restrict__ aw,
                            float* __restrict__ out) {
    __shared__ float saw[T1];
    __shared__ float red[512];
    int b = blockIdx.x, d = threadIdx.x;
    if (d < T1) saw[d] = aw[2 * H + d];
    __syncthreads();
    const float* xb = x + (size_t)b * T1 * D;
    float acc = 0.f;
    for (int t = 0; t < T1; t++) acc += xb[(size_t)t * D + d] * saw[t];
    red[d] = acc;
    __syncthreads();
    for (int s = 256; s > 0; s >>= 1) {
        if (d < s) red[d] = fmaxf(red[d], red[d + s]);
        __syncthreads();
    }
    float mx = red[0];
    __syncthreads();
    float e = expf(acc - mx);
    red[d] = e;
    __syncthreads();
    for (int s = 256; s > 0; s >>= 1) {
        if (d < s) red[d] += red[d + s];
        __syncthreads();
    }
    float a = e / red[0];
    float* ob = out + (size_t)b * T1 * D;
    for (int t = 0; t < T1; t++) {
        float w = a * xb[(size_t)t * D + d];
        ob[(size_t)t * D + d] = w;
        g_x[(size_t)b * T1 * D + (size_t)t * D + d] = __float2half(w);
    }
}

// ---------------------------------------------------------------------------
// pre0: [t][b][tilen*32 + q*8 + j] = weighted@Wih0^T + b_ih0 + b_hh0
// ---------------------------------------------------------------------------
__global__ void __launch_bounds__(NT) pre_gemm_kernel(const float* __restrict__ bih,
                                                      const float* __restrict__ bhh) {
    __shared__ __align__(128) char ring[3 * STG_BYTES];
    int tstep = blockIdx.x >> 2;
    int b0    = (blockIdx.x & 3) * 64;
    int tilec = blockIdx.y;
    int colbase = tilec * 16;
    const int lane = threadIdx.x & 31, warp = threadIdx.x >> 5;
    const int arow  = (warp >> 1) * 16 + (lane & 15);
    const int ahalf = lane >> 4;
    const int nrl   = (warp & 1) * 32 + ((lane >> 4) << 3) + (lane & 7);
    const int bhalf = (lane >> 3) & 1;
    const uint32_t sbase = (uint32_t)__cvta_generic_to_shared(ring);
    const hf* A0 = g_x + (size_t)tstep * D + (size_t)b0 * (T1 * D);

    float acc[4][4] = {};
    stage_chunk(A0, T1 * D, g_wih, colbase, sbase);
    CP_COMMIT();
    stage_chunk(A0 + 64, T1 * D, g_wih + 64, colbase, sbase + STG_BYTES);
    CP_COMMIT();
    for (int kc = 0; kc < 8; kc++) {
        CP_WAIT1();
        __syncthreads();
        if (kc + 2 < 8)
            stage_chunk(A0 + (kc + 2) * 64, T1 * D, g_wih + (kc + 2) * 64, colbase,
                        sbase + ((kc + 2) % 3) * STG_BYTES);
        CP_COMMIT();
        chunk_compute64(sbase + (uint32_t)((kc % 3) * STG_BYTES),
                        arow, ahalf, nrl, bhalf, acc);
    }
    __syncthreads();

    size_t base = (size_t)tstep * B * G;
#pragma unroll
    for (int nt = 0; nt < 4; nt++)
#pragma unroll
        for (int e = 0; e < 4; e++) {
            int r = (warp >> 1) * 16 + (lane >> 2) + ((e >> 1) ? 8 : 0);
            int c = (warp & 1) * 32 + nt * 8 + (lane & 3) * 2 + (e & 1);
            int bcol = ((c >> 4) << 9) + colbase + (c & 15);
            int idx = (tilec * 2 + ((c >> 3) & 1)) * 32 + ((c >> 4) << 3) + (c & 7);
            g_pre0[base + (size_t)(b0 + r) * G + idx] =
                acc[nt][e] + bih[bcol] + bhh[bcol];
        }
}

// ---------------------------------------------------------------------------
// Persistent wavefront kernel — M=128 x N=32, weights persistent in SMEM,
// A-segment sharing (24 chunks, shared h0/h1 A-fragments feed 2 B-segs),
// PER-WARP independent pipelines: warp w stages & reads only rows [16w,16w+16)
// => no __syncthreads in the chunk loop (cp.async.wait_group + __syncwarp).
// ---------------------------------------------------------------------------
#define NCA    24
#define WSEG_B 32768
#define ASTG_B 16384

__global__ void __launch_bounds__(NT, 1) lstm_kernel(const float* __restrict__ bih,
                                                     const float* __restrict__ bhh,
                                                     float* __restrict__ out) {
    __shared__ __align__(128) char wsm[5 * WSEG_B];    // 160KB persistent weights
    __shared__ __align__(128) char ring[3 * ASTG_B];   // 48KB A ring
    __shared__ float sbias[2][32];

    const int tid = threadIdx.x;
    const int warp = tid >> 5, lane = tid & 31;
    const int m     = blockIdx.x >> 6;        // 0..1
    const int tilen = blockIdx.x & 63;        // 0..63
    const int row0    = m * 128;
    const int colbase = tilen * 8;
    const int arow  = warp * 16 + (lane & 15);
    const int ahalf = lane >> 4;
    const int nrl   = ((lane >> 4) << 3) + (lane & 7);
    const int bhalf = (lane >> 3) & 1;
    const uint32_t wbase = (uint32_t)__cvta_generic_to_shared(wsm);
    const uint32_t rbase = (uint32_t)__cvta_generic_to_shared(ring);

    unsigned gen = *(volatile unsigned*)&g_rel;

    // zero both h parities (boundary waves read zeros)
    for (int idx = blockIdx.x * NT + tid; idx < 2 * NL * B * H; idx += GRID * NT)
        ((hf*)g_h)[idx] = __float2half(0.f);
    if (tid < 64) {
        int l = tid >> 5, c = tid & 31;
        int bcol = (l + 1) * G + ((c >> 3) << 9) + colbase + (c & 7);
        sbias[l][c] = bih[bcol] + bhh[bcol];
    }

    // one-time persistent weight load
    // seg: 0=Whh0 1=Whh1 2=Wih1 3=Whh2 4=Wih2 ; layout [seg][kchunk8][32r][64k]
    {
        const hf* wsrc[5] = { g_whh, g_whh + GH, g_wih + GH,
                              g_whh + 2 * GH, g_wih + 2 * GH };
#pragma unroll
        for (int it = 0; it < 40; it++) {
            int id = tid + it * NT;          // 0..10239
            int s   = id >> 11;
            int rem = id & 2047;
            int c = rem >> 8;
            int r = (rem >> 3) & 31;
            int k = rem & 7;
            int wrow = ((r >> 3) << 9) + colbase + (r & 7);
            uint32_t dst = wbase + (uint32_t)(s * WSEG_B + c * 4096 + r * 128
                          + ((k ^ (r & 7)) * 16));
            cp16u(dst, wsrc[s] + (size_t)wrow * 512 + c * 64 + k * 8);
        }
        CP_COMMIT();
        CP_WAITALL();
        __syncthreads();
    }

    float cst[NL][4];
#pragma unroll
    for (int l = 0; l < NL; l++)
#pragma unroll
        for (int e = 0; e < 4; e++) cst[l][e] = 0.f;

    const int rb = warp * 16 + (lane >> 2);
    const int j0 = (lane & 3) * 2;

    gbar(++gen);

    for (int w = 0; w < T1 + 2; w++) {
        const int np = w & 1, op = np ^ 1;
        // A source per chunk-group (0..2): h0, h1, h2
        const hf* agrp[3] = { g_h[op][0], g_h[op][1], g_h[op][2] };

        // warp-local staging: warp w stages ONLY its 16 rows
        auto stageA = [&](int ac) {
            int grp = ac >> 3, g = ac & 7;
            const hf* src = agrp[grp] + (size_t)(row0 + warp * 16) * H + g * 64;
            uint32_t st = rbase + (uint32_t)((ac % 3) * ASTG_B + warp * 2048);
#pragma unroll
            for (int u = 0; u < 4; u++) {
                int id = lane + u * 32;        // 0..127
                int r = id >> 3, k = id & 7;
                cp16u(st + (uint32_t)(r * 128 + ((k ^ (r & 7)) * 16)),
                      src + (size_t)r * H + k * 8);
            }
        };

        auto body = [&](int ac, uint32_t segP, float (&aP)[4][4],
                        uint32_t segQ, float (&aQ)[4][4], bool two) {
            CP_WAIT1();
            __syncwarp();
            if (ac + 2 < NCA) stageA(ac + 2);
            CP_COMMIT();
            uint32_t sbA = rbase + (uint32_t)((ac % 3) * ASTG_B);
            int g = ac & 7;
            uint32_t sbP = wbase + segP * WSEG_B + (uint32_t)(g * 4096);
            uint32_t sbQ = wbase + segQ * WSEG_B + (uint32_t)(g * 4096);
#pragma unroll
            for (int sub = 0; sub < 4; sub++) {
                uint32_t a[4];
                int aseg = (sub * 2 + ahalf) ^ (arow & 7);
                ldm4(sbA + (uint32_t)(arow * 128 + aseg * 16), a);
                int bs0 = (sub * 2 + bhalf) ^ (nrl & 7);
                int bs1 = (sub * 2 + bhalf) ^ ((nrl + 16) & 7);
                uint32_t b0[4], b1[4];
                ldm4(sbP + (uint32_t)(nrl * 128 + bs0 * 16), b0);
                ldm4(sbP + (uint32_t)((nrl + 16) * 128 + bs1 * 16), b1);
                mma16816(aP[0], a, b0[0], b0[1]);
                mma16816(aP[1], a, b0[2], b0[3]);
                mma16816(aP[2], a, b1[0], b1[1]);
                mma16816(aP[3], a, b1[2], b1[3]);
                if (two) {
                    uint32_t c0[4], c1[4];
                    ldm4(sbQ + (uint32_t)(nrl * 128 + bs0 * 16), c0);
                    ldm4(sbQ + (uint32_t)((nrl + 16) * 128 + bs1 * 16), c1);
                    mma16816(aQ[0], a, c0[0], c0[1]);
                    mma16816(aQ[1], a, c0[2], c0[3]);
                    mma16816(aQ[2], a, c1[0], c1[1]);
                    mma16816(aQ[3], a, c1[2], c1[3]);
                }
            }
        };

        float acc0[4][4] = {}, acc1[4][4] = {}, acc2[4][4] = {};
        stageA(0);
        CP_COMMIT();
        stageA(1);
        CP_COMMIT();
        // group 0: A=h0 -> Whh0(acc0) + Wih1(acc1)
        for (int ac = 0; ac < 8; ac++)   body(ac, 0u, acc0, 2u, acc1, true);
        // group 1: A=h1 -> Whh1(acc1) + Wih2(acc2)
        for (int ac = 8; ac < 16; ac++)  body(ac, 1u, acc1, 4u, acc2, true);
        // group 2: A=h2 -> Whh2(acc2)
        for (int ac = 16; ac < 24; ac++) body(ac, 3u, acc2, 3u, acc2, false);

        // register-resident cell update: l0@t=w, l1@t=w-1, l2@t=w-2
#pragma unroll
        for (int l = 0; l < NL; l++) {
            const int t = w - l;
            if (t < 0 || t >= T1) continue;
            float (&A)[4][4] = (l == 0) ? acc0 : (l == 1) ? acc1 : acc2;
            float add[4][2][2];   // [gate][er][ej]
            if (l == 0) {
                const float* p = g_pre0 + (size_t)t * B * G + tilen * 32;
#pragma unroll
                for (int er = 0; er < 2; er++) {
                    const float* pr = p + (size_t)(row0 + rb + er * 8) * G;
#pragma unroll
                    for (int q = 0; q < 4; q++) {
                        float2 v = *(const float2*)(pr + q * 8 + j0);
                        add[q][er][0] = v.x;
                        add[q][er][1] = v.y;
                    }
                }
            } else {
#pragma unroll
                for (int q = 0; q < 4; q++) {
                    float v0 = sbias[l - 1][q * 8 + j0];
                    float v1 = sbias[l - 1][q * 8 + j0 + 1];
                    add[q][0][0] = add[q][1][0] = v0;
                    add[q][0][1] = add[q][1][1] = v1;
                }
            }
#pragma unroll
            for (int er = 0; er < 2; er++) {
                hf h2v[2];
                float hnf[2];
#pragma unroll
                for (int ej = 0; ej < 2; ej++) {
                    int e = er * 2 + ej;
                    float gi = A[0][e] + add[0][er][ej];
                    float gf = A[1][e] + add[1][er][ej];
                    float gg = A[2][e] + add[2][er][ej];
                    float go = A[3][e] + add[3][er][ej];
                    float i_ = sigm(gi), f_ = sigm(gf);
                    float g_ = tanhf(gg), o_ = sigm(go);
                    float cn = f_ * cst[l][e] + i_ * g_;
                    float hn = o_ * tanhf(cn);
                    cst[l][e] = cn;
                    h2v[ej] = __float2half(hn);
                    hnf[ej] = hn;
                }
                int row = row0 + rb + er * 8;
                *(__half2*)&g_h[np][l][(size_t)row * H + colbase + j0] =
                    *(__half2*)h2v;
                if (l == NL - 1)
                    *(float2*)(out + OUT_ENC + (size_t)row * T1 * H
                               + (size_t)t * H + colbase + j0) =
                        make_float2(hnf[0], hnf[1]);
            }
        }
        gbar(++gen);
    }
}

// ---------------------------------------------------------------------------
extern "C" void kernel_launch(void* const* d_in, const int* in_sizes, int n_in,
                              void* d_out, int out_size) {
    const float* x   = (const float*)d_in[0];
    const float* wih = (const float*)d_in[1];
    const float* whh = (const float*)d_in[2];
    const float* bih = (const float*)d_in[3];
    const float* bhh = (const float*)d_in[4];
    const float* aw  = (const float*)d_in[5];
    float* out = (float*)d_out;

    split_w_kernel<<<(NL * GH + 255) / 256, 256>>>(wih, whh);
    attn_kernel<<<B, 512>>>(x, aw, out);
    dim3 pgrid(T1 * 4, G / 64);
    pre_gemm_kernel<<<pgrid, NT>>>(bih, bhh);
    lstm_kernel<<<GRID, NT>>>(bih, bhh, out);
}